// round 6
// baseline (speedup 1.0000x reference)
#include <cuda_runtime.h>

#define BSZ   8192
#define TLEN  256
#define OBS   8
#define NCTRL 2
#define HID   8
#define DIN   10
#define WIDTH 256
#define KSTEPS 32
#define T0    (TLEN - KSTEPS)

typedef unsigned long long ull;
typedef unsigned int uint;

__device__ float g_h[BSZ * HID];

__device__ __forceinline__ ull fma2(ull a, ull b, ull c) {
    ull d; asm("fma.rn.f32x2 %0,%1,%2,%3;" : "=l"(d) : "l"(a), "l"(b), "l"(c)); return d;
}
__device__ __forceinline__ ull pk(float x, float y) {
    ull r; asm("mov.b64 %0,{%1,%2};" : "=l"(r) : "f"(x), "f"(y)); return r;
}
__device__ __forceinline__ void upk(ull v, float& x, float& y) {
    asm("mov.b64 {%0,%1},%2;" : "=f"(x), "=f"(y) : "l"(v));
}
__device__ __forceinline__ float sigmoidf(float y) {
    float e = __expf(-y);
    float r; asm("rcp.approx.f32 %0,%1;" : "=f"(r) : "f"(1.f + e));
    return r;
}
__device__ __forceinline__ float tf32f(float x) {
    uint r; asm("cvt.rna.tf32.f32 %0,%1;" : "=r"(r) : "f"(x));
    return __uint_as_float(r);
}

// ---------------------------------------------------------------------------
// Front: u = W_B x via shared staging (coalesced), 32-step scan, and
// out[] initialization to b2 (decoder col-blocks atomicAdd partials later).
// ---------------------------------------------------------------------------
#define SUI(t, i, bl) ((t) * 274 + (i) * 34 + (bl))

__global__ __launch_bounds__(256) void front_kernel(
    const float* __restrict__ state, const float* __restrict__ ctrl,
    const float* __restrict__ WA, const float* __restrict__ WB,
    const float* __restrict__ b2, float* __restrict__ out)
{
    __shared__ float su[32 * 274];
    const int tid = threadIdx.x;
    const int b0  = blockIdx.x * 32;

    {
        float Bw[HID][DIN];
#pragma unroll
        for (int i = 0; i < HID; i++)
#pragma unroll
            for (int k = 0; k < DIN; k++) Bw[i][k] = WB[i * DIN + k];

        float4 s0[4], s1[4]; float2 cv[4];
#pragma unroll
        for (int it = 0; it < 4; it++) {
            const int t  = tid & 31;
            const int bl = it * 8 + (tid >> 5);
            const size_t row = (size_t)(b0 + bl) * TLEN + T0 + t;
            const float4* sp = reinterpret_cast<const float4*>(state + row * OBS);
            s0[it] = sp[0]; s1[it] = sp[1];
            cv[it] = *reinterpret_cast<const float2*>(ctrl + row * NCTRL);
        }
#pragma unroll
        for (int it = 0; it < 4; it++) {
            const int t  = tid & 31;
            const int bl = it * 8 + (tid >> 5);
            float x[DIN] = {s0[it].x, s0[it].y, s0[it].z, s0[it].w,
                            s1[it].x, s1[it].y, s1[it].z, s1[it].w,
                            cv[it].x, cv[it].y};
#pragma unroll
            for (int i = 0; i < HID; i++) {
                float acc = 0.f;
#pragma unroll
                for (int k = 0; k < DIN; k++) acc = fmaf(Bw[i][k], x[k], acc);
                su[SUI(t, i, bl)] = acc;
            }
        }
    }
    __syncthreads();
    if (tid >= 32) return;

    const int bl = tid;
    ull Adual[HID][4];
#pragma unroll
    for (int j = 0; j < HID; j++)
#pragma unroll
        for (int p = 0; p < 4; p++)
            Adual[j][p] = pk(WA[(2 * p) * HID + j], WA[(2 * p + 1) * HID + j]);

    float h[HID];
#pragma unroll
    for (int i = 0; i < HID; i++) h[i] = 0.f;

#pragma unroll 4
    for (int t = 0; t < KSTEPS; t++) {
        float u[HID];
#pragma unroll
        for (int i = 0; i < HID; i++) u[i] = su[SUI(t, i, bl)];
        ull acc[4];
#pragma unroll
        for (int p = 0; p < 4; p++) acc[p] = pk(u[2 * p], u[2 * p + 1]);
#pragma unroll
        for (int j = 0; j < HID; j++) {
            ull hd = pk(h[j], h[j]);
#pragma unroll
            for (int p = 0; p < 4; p++) acc[p] = fma2(Adual[j][p], hd, acc[p]);
        }
#pragma unroll
        for (int p = 0; p < 4; p++) {
            float y0, y1; upk(acc[p], y0, y1);
            h[2 * p]     = sigmoidf(y0);
            h[2 * p + 1] = sigmoidf(y1);
        }
    }
    float4* gh = reinterpret_cast<float4*>(g_h + (size_t)(b0 + bl) * HID);
    gh[0] = make_float4(h[0], h[1], h[2], h[3]);
    gh[1] = make_float4(h[4], h[5], h[6], h[7]);
    out[b0 + bl] = b2[0];   // init for decoder's atomic partial sums
}

// ---------------------------------------------------------------------------
// Decoder: grid (4 col-blocks, 128 row-blocks). Block = m64 rows x n64 cols,
// K=256. Layer1 recomputed per col-block (cheap); layer2 tf32 mma.sync;
// layer3 partials -> global atomicAdd. Warp tile m16 x n32 (4m x 2n warps).
// W tiled KC=128 through shared (2 stages). All LDS.128 conflict-free.
// ---------------------------------------------------------------------------
#define DEC_T  256
#define RPB    64
#define NPB    64
#define KC     128
#define XS_OFF  0
#define A1P_OFF (RPB * DIN)                  // 640
#define A1P_SZ  (4 * 4224)                   // 16896
#define WQ_OFF  (A1P_OFF + A1P_SZ)           // 17536
#define WQ_SZ   (8 * 1056)                   // 8448
#define SMEMF   (WQ_OFF + WQ_SZ)             // 25984 floats = 103936 B

#define A1P(mi, k8, ln, reg) (A1P_OFF + (mi) * 4224 + (k8) * 132 + (ln) * 4 + (reg))
#define WQI(q, tg, n, e)     (WQ_OFF + (q) * 1056 + (tg) * 264 + (n) * 4 + (e))

__device__ __forceinline__ void mma_tf32(
    float& d0, float& d1, float& d2, float& d3,
    uint a0, uint a1, uint a2, uint a3, uint b0, uint b1)
{
    asm("mma.sync.aligned.m16n8k8.row.col.f32.tf32.tf32.f32 "
        "{%0,%1,%2,%3}, {%4,%5,%6,%7}, {%8,%9}, {%0,%1,%2,%3};"
        : "+f"(d0), "+f"(d1), "+f"(d2), "+f"(d3)
        : "r"(a0), "r"(a1), "r"(a2), "r"(a3), "r"(b0), "r"(b1));
}

__global__ __launch_bounds__(DEC_T) void decoder_kernel(
    const float* __restrict__ control,
    const float* __restrict__ W0, const float* __restrict__ b0v,
    const float* __restrict__ W1, const float* __restrict__ b1,
    const float* __restrict__ W2,
    float* __restrict__ out)
{
    extern __shared__ float sm[];
    const int tid  = threadIdx.x;
    const int nb   = blockIdx.x;           // column block: cols nb*64..+63
    const int row0 = blockIdx.y * RPB;

    // stage x = [h, control]
    for (int i = tid; i < RPB * DIN; i += DEC_T) {
        int r = i / DIN, k = i % DIN;
        sm[XS_OFF + i] = (k < HID) ? g_h[(row0 + r) * HID + k]
                                   : control[(row0 + r) * NCTRL + (k - HID)];
    }
    __syncthreads();

    // ---- layer 1: thread = column c (GEMM k index); mma-permuted tf32 A ----
    {
        const int c   = tid;
        const int k8c = c >> 3, tgc = c & 3, khc = (c >> 2) & 1;
        float w0[DIN];
#pragma unroll
        for (int k = 0; k < DIN; k++) w0[k] = W0[c * DIN + k];
        const float bb = b0v[c];
#pragma unroll
        for (int mi = 0; mi < 4; mi++) {
#pragma unroll
            for (int g = 0; g < 8; g++) {
                const int r = mi * 16 + g;
                float sA = bb, sB = bb;
#pragma unroll
                for (int k = 0; k < DIN; k++) {
                    sA = fmaf(w0[k], sm[XS_OFF + r * DIN + k], sA);
                    sB = fmaf(w0[k], sm[XS_OFF + (r + 8) * DIN + k], sB);
                }
                float vA = tf32f(fmaxf(sA, 0.f));
                float vB = tf32f(fmaxf(sB, 0.f));
                *reinterpret_cast<ull*>(&sm[A1P(mi, k8c, g * 4 + tgc, 2 * khc)]) = pk(vA, vB);
            }
        }
    }

    const int lane = tid & 31;
    const int wrp  = tid >> 5;
    const int wm   = wrp & 3;       // m16 group (rows wm*16..+15)
    const int nh   = wrp >> 2;      // n32 half (cols nh*32..+31 local)
    const int g    = lane >> 2;
    const int tg   = lane & 3;

    float acc[4][4];
#pragma unroll
    for (int t = 0; t < 4; t++)
#pragma unroll
        for (int e = 0; e < 4; e++) acc[t][e] = 0.f;

    const int sn = tid >> 2;        // staging: col (local)
    const int qd = tid & 3;         // staging: quarter of k-range

    for (int kt = 0; kt < WIDTH / KC; kt++) {
        __syncthreads();
        // stage W1[nb*64 + n][kt*128 .. +127] -> k16-quad tf32 layout
        {
            const float4* wrow = reinterpret_cast<const float4*>(
                W1 + (size_t)(nb * NPB + sn) * WIDTH + kt * KC);
#pragma unroll
            for (int j = 0; j < 8; j++) {
                const int f = qd + j * 4;        // float4 index 0..31
                float4 v = wrow[f];
                const int kl = f * 4;
                const int q = kl >> 4, e = (kl >> 2) & 3;
                sm[WQI(q, 0, sn, e)] = tf32f(v.x);
                sm[WQI(q, 1, sn, e)] = tf32f(v.y);
                sm[WQI(q, 2, sn, e)] = tf32f(v.z);
                sm[WQI(q, 3, sn, e)] = tf32f(v.w);
            }
        }
        __syncthreads();

#pragma unroll
        for (int q = 0; q < KC / 16; q++) {
            const int k8a = kt * (KC / 8) + 2 * q;
            float4 fa = *reinterpret_cast<const float4*>(&sm[A1P(wm, k8a, lane, 0)]);
            float4 fb = *reinterpret_cast<const float4*>(&sm[A1P(wm, k8a + 1, lane, 0)]);
            uint a00 = __float_as_uint(fa.x), a01 = __float_as_uint(fa.y);
            uint a02 = __float_as_uint(fa.z), a03 = __float_as_uint(fa.w);
            uint a10 = __float_as_uint(fb.x), a11 = __float_as_uint(fb.y);
            uint a12 = __float_as_uint(fb.z), a13 = __float_as_uint(fb.w);
#pragma unroll
            for (int t = 0; t < 4; t++) {
                const int n = nh * 32 + t * 8 + g;
                float4 bv = *reinterpret_cast<const float4*>(&sm[WQI(q, tg, n, 0)]);
                mma_tf32(acc[t][0], acc[t][1], acc[t][2], acc[t][3],
                         a00, a01, a02, a03,
                         __float_as_uint(bv.x), __float_as_uint(bv.y));
                mma_tf32(acc[t][0], acc[t][1], acc[t][2], acc[t][3],
                         a10, a11, a12, a13,
                         __float_as_uint(bv.z), __float_as_uint(bv.w));
            }
        }
    }

    // ---- epilogue: bias + relu + dot W2 partials, reduce tg, global atomics
    float qa = 0.f, qb = 0.f;        // rows wm*16+g, +8
#pragma unroll
    for (int t = 0; t < 4; t++) {
        const int c0 = nb * NPB + nh * 32 + t * 8 + 2 * tg;
        float2 bb = *reinterpret_cast<const float2*>(b1 + c0);
        float2 ww = *reinterpret_cast<const float2*>(W2 + c0);
        qa = fmaf(ww.x, fmaxf(acc[t][0] + bb.x, 0.f), qa);
        qa = fmaf(ww.y, fmaxf(acc[t][1] + bb.y, 0.f), qa);
        qb = fmaf(ww.x, fmaxf(acc[t][2] + bb.x, 0.f), qb);
        qb = fmaf(ww.y, fmaxf(acc[t][3] + bb.y, 0.f), qb);
    }
    qa += __shfl_xor_sync(0xffffffffu, qa, 1);
    qa += __shfl_xor_sync(0xffffffffu, qa, 2);
    qb += __shfl_xor_sync(0xffffffffu, qb, 1);
    qb += __shfl_xor_sync(0xffffffffu, qb, 2);
    if (tg == 0) {
        atomicAdd(&out[row0 + wm * 16 + g], qa);
        atomicAdd(&out[row0 + wm * 16 + g + 8], qb);
    }
}

// ---------------------------------------------------------------------------
extern "C" void kernel_launch(void* const* d_in, const int* in_sizes, int n_in,
                              void* d_out, int out_size)
{
    const float* state   = (const float*)d_in[0];
    const float* ctrlseq = (const float*)d_in[1];
    const float* control = (const float*)d_in[2];
    const float* WA      = (const float*)d_in[3];
    const float* WB      = (const float*)d_in[4];
    const float* W0      = (const float*)d_in[5];
    const float* b0      = (const float*)d_in[6];
    const float* W1      = (const float*)d_in[7];
    const float* b1      = (const float*)d_in[8];
    const float* W2      = (const float*)d_in[9];
    const float* b2      = (const float*)d_in[10];
    float* out           = (float*)d_out;

    const int smem_bytes = SMEMF * (int)sizeof(float);   // 103936 B
    cudaFuncSetAttribute(decoder_kernel,
                         cudaFuncAttributeMaxDynamicSharedMemorySize, smem_bytes);

    front_kernel<<<BSZ / 32, 256>>>(state, ctrlseq, WA, WB, b2, out);
    dim3 dgrid(WIDTH / NPB, BSZ / RPB);   // (4, 128)
    decoder_kernel<<<dgrid, DEC_T, smem_bytes>>>(
        control, W0, b0, W1, b1, W2, out);
    (void)in_sizes; (void)n_in; (void)out_size;
}

// round 7
// speedup vs baseline: 1.0994x; 1.0994x over previous
#include <cuda_runtime.h>

#define BSZ   8192
#define TLEN  256
#define OBS   8
#define NCTRL 2
#define HID   8
#define DIN   10
#define WIDTH 256
#define KSTEPS 32
#define T0    (TLEN - KSTEPS)

typedef unsigned long long ull;
typedef unsigned int uint;

__device__ float g_h[BSZ * HID];

__device__ __forceinline__ ull fma2(ull a, ull b, ull c) {
    ull d; asm("fma.rn.f32x2 %0,%1,%2,%3;" : "=l"(d) : "l"(a), "l"(b), "l"(c)); return d;
}
__device__ __forceinline__ ull pk(float x, float y) {
    ull r; asm("mov.b64 %0,{%1,%2};" : "=l"(r) : "f"(x), "f"(y)); return r;
}
__device__ __forceinline__ void upk(ull v, float& x, float& y) {
    asm("mov.b64 {%0,%1},%2;" : "=f"(x), "=f"(y) : "l"(v));
}
__device__ __forceinline__ float sigmoidf(float y) {
    float e = __expf(-y);
    float r; asm("rcp.approx.f32 %0,%1;" : "=f"(r) : "f"(1.f + e));
    return r;
}
__device__ __forceinline__ float tf32f(float x) {
    uint r; asm("cvt.rna.tf32.f32 %0,%1;" : "=r"(r) : "f"(x));
    return __uint_as_float(r);
}

// ---------------------------------------------------------------------------
// Front: u = W_B x via shared staging (coalesced), then 32-step scan.
// ---------------------------------------------------------------------------
#define SUI(t, i, bl) ((t) * 274 + (i) * 34 + (bl))

__global__ __launch_bounds__(256) void front_kernel(
    const float* __restrict__ state, const float* __restrict__ ctrl,
    const float* __restrict__ WA, const float* __restrict__ WB)
{
    __shared__ float su[32 * 274];
    const int tid = threadIdx.x;
    const int b0  = blockIdx.x * 32;

    {
        float Bw[HID][DIN];
#pragma unroll
        for (int i = 0; i < HID; i++)
#pragma unroll
            for (int k = 0; k < DIN; k++) Bw[i][k] = WB[i * DIN + k];

        float4 s0[4], s1[4]; float2 cv[4];
#pragma unroll
        for (int it = 0; it < 4; it++) {
            const int t  = tid & 31;
            const int bl = it * 8 + (tid >> 5);
            const size_t row = (size_t)(b0 + bl) * TLEN + T0 + t;
            const float4* sp = reinterpret_cast<const float4*>(state + row * OBS);
            s0[it] = sp[0]; s1[it] = sp[1];
            cv[it] = *reinterpret_cast<const float2*>(ctrl + row * NCTRL);
        }
#pragma unroll
        for (int it = 0; it < 4; it++) {
            const int t  = tid & 31;
            const int bl = it * 8 + (tid >> 5);
            float x[DIN] = {s0[it].x, s0[it].y, s0[it].z, s0[it].w,
                            s1[it].x, s1[it].y, s1[it].z, s1[it].w,
                            cv[it].x, cv[it].y};
#pragma unroll
            for (int i = 0; i < HID; i++) {
                float acc = 0.f;
#pragma unroll
                for (int k = 0; k < DIN; k++) acc = fmaf(Bw[i][k], x[k], acc);
                su[SUI(t, i, bl)] = acc;
            }
        }
    }
    __syncthreads();
    if (tid >= 32) return;

    const int bl = tid;
    ull Adual[HID][4];
#pragma unroll
    for (int j = 0; j < HID; j++)
#pragma unroll
        for (int p = 0; p < 4; p++)
            Adual[j][p] = pk(WA[(2 * p) * HID + j], WA[(2 * p + 1) * HID + j]);

    float h[HID];
#pragma unroll
    for (int i = 0; i < HID; i++) h[i] = 0.f;

#pragma unroll 4
    for (int t = 0; t < KSTEPS; t++) {
        float u[HID];
#pragma unroll
        for (int i = 0; i < HID; i++) u[i] = su[SUI(t, i, bl)];
        ull acc[4];
#pragma unroll
        for (int p = 0; p < 4; p++) acc[p] = pk(u[2 * p], u[2 * p + 1]);
#pragma unroll
        for (int j = 0; j < HID; j++) {
            ull hd = pk(h[j], h[j]);
#pragma unroll
            for (int p = 0; p < 4; p++) acc[p] = fma2(Adual[j][p], hd, acc[p]);
        }
#pragma unroll
        for (int p = 0; p < 4; p++) {
            float y0, y1; upk(acc[p], y0, y1);
            h[2 * p]     = sigmoidf(y0);
            h[2 * p + 1] = sigmoidf(y1);
        }
    }
    float4* gh = reinterpret_cast<float4*>(g_h + (size_t)(b0 + bl) * HID);
    gh[0] = make_float4(h[0], h[1], h[2], h[3]);
    gh[1] = make_float4(h[4], h[5], h[6], h[7]);
}

// ---------------------------------------------------------------------------
// Decoder: 128 blocks x 512 threads (16 warps), m64 rows x full n256, K=256.
// Layer1 once per block (split across the two 256-thread halves); layer2 tf32
// mma.sync with KC=32 W tiles staged via register-transpose + STS.128;
// layer3 fused, qsm shared reduction. Warp tile m16 x n64 (wm=wrp&3, nq=wrp>>2).
// ---------------------------------------------------------------------------
#define DEC_T  512
#define RPB    64
#define KC     32
#define XS_OFF  0
#define QS_OFF  (RPB * DIN)                  // 640
#define A1P_OFF (QS_OFF + RPB)               // 704
#define A1P_SZ  (4 * 4224)                   // 16896
#define WQ_OFF  (A1P_OFF + A1P_SZ)           // 17600
#define WQ_SZ   (2 * 4136)                   // 8272
#define SMEMF   (WQ_OFF + WQ_SZ)             // 25872 floats = 103488 B

#define A1P(mi, k8, ln, reg) (A1P_OFF + (mi) * 4224 + (k8) * 132 + (ln) * 4 + (reg))
#define WQI(q, tg, n, e)     (WQ_OFF + (q) * 4136 + (tg) * 1032 + (n) * 4 + (e))

__device__ __forceinline__ void mma_tf32(
    float& d0, float& d1, float& d2, float& d3,
    uint a0, uint a1, uint a2, uint a3, uint b0, uint b1)
{
    asm("mma.sync.aligned.m16n8k8.row.col.f32.tf32.tf32.f32 "
        "{%0,%1,%2,%3}, {%4,%5,%6,%7}, {%8,%9}, {%0,%1,%2,%3};"
        : "+f"(d0), "+f"(d1), "+f"(d2), "+f"(d3)
        : "r"(a0), "r"(a1), "r"(a2), "r"(a3), "r"(b0), "r"(b1));
}

__global__ __launch_bounds__(DEC_T) void decoder_kernel(
    const float* __restrict__ control,
    const float* __restrict__ W0, const float* __restrict__ b0v,
    const float* __restrict__ W1, const float* __restrict__ b1,
    const float* __restrict__ W2, const float* __restrict__ b2,
    float* __restrict__ out)
{
    extern __shared__ float sm[];
    const int tid  = threadIdx.x;
    const int row0 = blockIdx.x * RPB;

    if (tid < RPB) sm[QS_OFF + tid] = 0.f;
    for (int i = tid; i < RPB * DIN; i += DEC_T) {
        int r = i / DIN, k = i % DIN;
        sm[XS_OFF + i] = (k < HID) ? g_h[(row0 + r) * HID + k]
                                   : control[(row0 + r) * NCTRL + (k - HID)];
    }
    __syncthreads();

    // ---- layer 1: thread (c = tid&255) does 2 of 4 m-tiles (half = tid>>8)
    {
        const int c    = tid & 255;
        const int half = tid >> 8;
        const int k8c = c >> 3, tgc = c & 3, khc = (c >> 2) & 1;
        float w0[DIN];
#pragma unroll
        for (int k = 0; k < DIN; k++) w0[k] = W0[c * DIN + k];
        const float bb = b0v[c];
#pragma unroll
        for (int mm = 0; mm < 2; mm++) {
            const int mi = half * 2 + mm;
#pragma unroll
            for (int g = 0; g < 8; g++) {
                const int r = mi * 16 + g;
                float sA = bb, sB = bb;
#pragma unroll
                for (int k = 0; k < DIN; k++) {
                    sA = fmaf(w0[k], sm[XS_OFF + r * DIN + k], sA);
                    sB = fmaf(w0[k], sm[XS_OFF + (r + 8) * DIN + k], sB);
                }
                float vA = tf32f(fmaxf(sA, 0.f));
                float vB = tf32f(fmaxf(sB, 0.f));
                *reinterpret_cast<ull*>(&sm[A1P(mi, k8c, g * 4 + tgc, 2 * khc)]) = pk(vA, vB);
            }
        }
    }

    const int lane = tid & 31;
    const int wrp  = tid >> 5;
    const int wm   = wrp & 3;       // m16 group (rows wm*16..+15)
    const int nq   = wrp >> 2;      // n64 quarter (cols nq*64..+63)
    const int g    = lane >> 2;
    const int tg   = lane & 3;

    float acc[8][4];
#pragma unroll
    for (int t = 0; t < 8; t++)
#pragma unroll
        for (int e = 0; e < 4; e++) acc[t][e] = 0.f;

    const int sn = tid >> 1;        // staging: W1 row (0..255)
    const int kd = tid & 1;         // staging: k16 half of the KC=32 tile

    for (int kt = 0; kt < WIDTH / KC; kt++) {   // 8 tiles
        __syncthreads();
        // stage: load 4 float4 of row sn, k range kt*32 + kd*16; transpose in
        // regs; 4x STS.128 (conflict-free) into k16-quad tf32 layout.
        {
            const float4* wrow = reinterpret_cast<const float4*>(
                W1 + (size_t)sn * WIDTH + kt * KC + kd * 16);
            float4 v0 = wrow[0], v1 = wrow[1], v2 = wrow[2], v3 = wrow[3];
            float4 o;
            o = make_float4(tf32f(v0.x), tf32f(v1.x), tf32f(v2.x), tf32f(v3.x));
            *reinterpret_cast<float4*>(&sm[WQI(kd, 0, sn, 0)]) = o;
            o = make_float4(tf32f(v0.y), tf32f(v1.y), tf32f(v2.y), tf32f(v3.y));
            *reinterpret_cast<float4*>(&sm[WQI(kd, 1, sn, 0)]) = o;
            o = make_float4(tf32f(v0.z), tf32f(v1.z), tf32f(v2.z), tf32f(v3.z));
            *reinterpret_cast<float4*>(&sm[WQI(kd, 2, sn, 0)]) = o;
            o = make_float4(tf32f(v0.w), tf32f(v1.w), tf32f(v2.w), tf32f(v3.w));
            *reinterpret_cast<float4*>(&sm[WQI(kd, 3, sn, 0)]) = o;
        }
        __syncthreads();

#pragma unroll
        for (int q = 0; q < 2; q++) {           // k16 groups in tile
            const int k8a = kt * 4 + 2 * q;
            float4 fa = *reinterpret_cast<const float4*>(&sm[A1P(wm, k8a, lane, 0)]);
            float4 fb = *reinterpret_cast<const float4*>(&sm[A1P(wm, k8a + 1, lane, 0)]);
            uint a00 = __float_as_uint(fa.x), a01 = __float_as_uint(fa.y);
            uint a02 = __float_as_uint(fa.z), a03 = __float_as_uint(fa.w);
            uint a10 = __float_as_uint(fb.x), a11 = __float_as_uint(fb.y);
            uint a12 = __float_as_uint(fb.z), a13 = __float_as_uint(fb.w);
#pragma unroll
            for (int t = 0; t < 8; t++) {
                const int n = nq * 64 + t * 8 + g;
                float4 bv = *reinterpret_cast<const float4*>(&sm[WQI(q, tg, n, 0)]);
                mma_tf32(acc[t][0], acc[t][1], acc[t][2], acc[t][3],
                         a00, a01, a02, a03,
                         __float_as_uint(bv.x), __float_as_uint(bv.y));
                mma_tf32(acc[t][0], acc[t][1], acc[t][2], acc[t][3],
                         a10, a11, a12, a13,
                         __float_as_uint(bv.z), __float_as_uint(bv.w));
            }
        }
    }

    // ---- epilogue: bias + relu + dot W2 over this warp's n64, reduce tg ----
    float qa = 0.f, qb = 0.f;        // rows wm*16+g, +8
#pragma unroll
    for (int t = 0; t < 8; t++) {
        const int c0 = nq * 64 + t * 8 + 2 * tg;
        float2 bb = *reinterpret_cast<const float2*>(b1 + c0);
        float2 ww = *reinterpret_cast<const float2*>(W2 + c0);
        qa = fmaf(ww.x, fmaxf(acc[t][0] + bb.x, 0.f), qa);
        qa = fmaf(ww.y, fmaxf(acc[t][1] + bb.y, 0.f), qa);
        qb = fmaf(ww.x, fmaxf(acc[t][2] + bb.x, 0.f), qb);
        qb = fmaf(ww.y, fmaxf(acc[t][3] + bb.y, 0.f), qb);
    }
    qa += __shfl_xor_sync(0xffffffffu, qa, 1);
    qa += __shfl_xor_sync(0xffffffffu, qa, 2);
    qb += __shfl_xor_sync(0xffffffffu, qb, 1);
    qb += __shfl_xor_sync(0xffffffffu, qb, 2);
    if (tg == 0) {
        atomicAdd(&sm[QS_OFF + wm * 16 + g], qa);
        atomicAdd(&sm[QS_OFF + wm * 16 + g + 8], qb);
    }
    __syncthreads();
    if (tid < RPB)
        out[row0 + tid] = sm[QS_OFF + tid] + b2[0];
}

// ---------------------------------------------------------------------------
extern "C" void kernel_launch(void* const* d_in, const int* in_sizes, int n_in,
                              void* d_out, int out_size)
{
    const float* state   = (const float*)d_in[0];
    const float* ctrlseq = (const float*)d_in[1];
    const float* control = (const float*)d_in[2];
    const float* WA      = (const float*)d_in[3];
    const float* WB      = (const float*)d_in[4];
    const float* W0      = (const float*)d_in[5];
    const float* b0      = (const float*)d_in[6];
    const float* W1      = (const float*)d_in[7];
    const float* b1      = (const float*)d_in[8];
    const float* W2      = (const float*)d_in[9];
    const float* b2      = (const float*)d_in[10];
    float* out           = (float*)d_out;

    const int smem_bytes = SMEMF * (int)sizeof(float);   // 103488 B
    cudaFuncSetAttribute(decoder_kernel,
                         cudaFuncAttributeMaxDynamicSharedMemorySize, smem_bytes);

    front_kernel<<<BSZ / 32, 256>>>(state, ctrlseq, WA, WB);
    decoder_kernel<<<BSZ / RPB, DEC_T, smem_bytes>>>(
        control, W0, b0, W1, b1, W2, b2, out);
    (void)in_sizes; (void)n_in; (void)out_size;
}

// round 8
// speedup vs baseline: 1.2264x; 1.1156x over previous
#include <cuda_runtime.h>

#define BSZ   8192
#define TLEN  256
#define OBS   8
#define NCTRL 2
#define HID   8
#define DIN   10
#define WIDTH 256
#define KSTEPS 32
#define T0    (TLEN - KSTEPS)

typedef unsigned long long ull;
typedef unsigned int uint;

__device__ __forceinline__ ull fma2(ull a, ull b, ull c) {
    ull d; asm("fma.rn.f32x2 %0,%1,%2,%3;" : "=l"(d) : "l"(a), "l"(b), "l"(c)); return d;
}
__device__ __forceinline__ ull pk(float x, float y) {
    ull r; asm("mov.b64 %0,{%1,%2};" : "=l"(r) : "f"(x), "f"(y)); return r;
}
__device__ __forceinline__ void upk(ull v, float& x, float& y) {
    asm("mov.b64 {%0,%1},%2;" : "=f"(x), "=f"(y) : "l"(v));
}
__device__ __forceinline__ float sigmoidf(float y) {
    float e = __expf(-y);
    float r; asm("rcp.approx.f32 %0,%1;" : "=f"(r) : "f"(1.f + e));
    return r;
}
__device__ __forceinline__ float tf32f(float x) {
    uint r; asm("cvt.rna.tf32.f32 %0,%1;" : "=r"(r) : "f"(x));
    return __uint_as_float(r);
}
__device__ __forceinline__ void mma_tf32(
    float& d0, float& d1, float& d2, float& d3,
    uint a0, uint a1, uint a2, uint a3, uint b0, uint b1)
{
    asm("mma.sync.aligned.m16n8k8.row.col.f32.tf32.tf32.f32 "
        "{%0,%1,%2,%3}, {%4,%5,%6,%7}, {%8,%9}, {%0,%1,%2,%3};"
        : "+f"(d0), "+f"(d1), "+f"(d2), "+f"(d3)
        : "r"(a0), "r"(a1), "r"(a2), "r"(a3), "r"(b0), "r"(b1));
}

// ---------------------------------------------------------------------------
// Fully fused: [stage u -> scan -> layer1 -> tf32 MMA layer2 (double-buffered
// W tiles, B-frag prefetch) -> layer3]. 128 blocks x 512 threads, 64 rows/blk.
// ---------------------------------------------------------------------------
#define DEC_T  512
#define RPB    64
#define KC     32
#define XS_OFF  0
#define QS_OFF  (RPB * DIN)                  // 640
#define A1P_OFF (QS_OFF + RPB)               // 704
#define A1P_SZ  (4 * 4224)                   // 16896
#define WQ_OFF  (A1P_OFF + A1P_SZ)           // 17600
#define WQ_SZ   (2 * 8272)                   // double-buffered: 16544
#define SMEMF   (WQ_OFF + WQ_SZ)             // 34144 floats = 136576 B

#define A1P(mi, k8, ln, reg) (A1P_OFF + (mi) * 4224 + (k8) * 132 + (ln) * 4 + (reg))
#define WQI(buf, q, tg, n, e) (WQ_OFF + (buf) * 8272 + (q) * 4136 + (tg) * 1032 + (n) * 4 + (e))
// scan staging aliases A1P/WQ region (dead before layer1/W-staging write it)
#define SUI(t, i, bl) (A1P_OFF + (t) * 529 + (i) * 66 + (bl))

__global__ __launch_bounds__(DEC_T) void fused_kernel(
    const float* __restrict__ state, const float* __restrict__ ctrl,
    const float* __restrict__ control,
    const float* __restrict__ WA, const float* __restrict__ WB,
    const float* __restrict__ W0, const float* __restrict__ b0v,
    const float* __restrict__ W1, const float* __restrict__ b1,
    const float* __restrict__ W2, const float* __restrict__ b2,
    float* __restrict__ out)
{
    extern __shared__ float sm[];
    const int tid  = threadIdx.x;
    const int row0 = blockIdx.x * RPB;

    // ======== front: stage u = W_B x (coalesced), 2048 items / 512 thr ======
    {
        float Bw[HID][DIN];
#pragma unroll
        for (int i = 0; i < HID; i++)
#pragma unroll
            for (int k = 0; k < DIN; k++) Bw[i][k] = WB[i * DIN + k];

        float4 s0[4], s1[4]; float2 cv[4];
#pragma unroll
        for (int it = 0; it < 4; it++) {
            const int item = it * DEC_T + tid;
            const int bl = item >> 5, t = item & 31;
            const size_t row = (size_t)(row0 + bl) * TLEN + T0 + t;
            const float4* sp = reinterpret_cast<const float4*>(state + row * OBS);
            s0[it] = sp[0]; s1[it] = sp[1];
            cv[it] = *reinterpret_cast<const float2*>(ctrl + row * NCTRL);
        }
#pragma unroll
        for (int it = 0; it < 4; it++) {
            const int item = it * DEC_T + tid;
            const int bl = item >> 5, t = item & 31;
            float x[DIN] = {s0[it].x, s0[it].y, s0[it].z, s0[it].w,
                            s1[it].x, s1[it].y, s1[it].z, s1[it].w,
                            cv[it].x, cv[it].y};
#pragma unroll
            for (int i = 0; i < HID; i++) {
                float acc = 0.f;
#pragma unroll
                for (int k = 0; k < DIN; k++) acc = fmaf(Bw[i][k], x[k], acc);
                sm[SUI(t, i, bl)] = acc;
            }
        }
    }
    __syncthreads();

    // ======== scan (warps 0-1) || control staging + qs init (others) ========
    if (tid < 64) {
        const int bl = tid;
        ull Adual[HID][4];
#pragma unroll
        for (int j = 0; j < HID; j++)
#pragma unroll
            for (int p = 0; p < 4; p++)
                Adual[j][p] = pk(WA[(2 * p) * HID + j], WA[(2 * p + 1) * HID + j]);

        float h[HID];
#pragma unroll
        for (int i = 0; i < HID; i++) h[i] = 0.f;
#pragma unroll 4
        for (int t = 0; t < KSTEPS; t++) {
            float u[HID];
#pragma unroll
            for (int i = 0; i < HID; i++) u[i] = sm[SUI(t, i, bl)];
            ull acc[4];
#pragma unroll
            for (int p = 0; p < 4; p++) acc[p] = pk(u[2 * p], u[2 * p + 1]);
#pragma unroll
            for (int j = 0; j < HID; j++) {
                ull hd = pk(h[j], h[j]);
#pragma unroll
                for (int p = 0; p < 4; p++) acc[p] = fma2(Adual[j][p], hd, acc[p]);
            }
#pragma unroll
            for (int p = 0; p < 4; p++) {
                float y0, y1; upk(acc[p], y0, y1);
                h[2 * p]     = sigmoidf(y0);
                h[2 * p + 1] = sigmoidf(y1);
            }
        }
#pragma unroll
        for (int i = 0; i < HID; i++) sm[XS_OFF + bl * DIN + i] = h[i];
    } else if (tid < 192) {
        const int i = tid - 64;                 // 128 items: 64 rows x 2 ctrl
        const int r = i >> 1, k = i & 1;
        sm[XS_OFF + r * DIN + HID + k] = control[(row0 + r) * NCTRL + k];
    } else if (tid < 256) {
        sm[QS_OFF + (tid - 192)] = 0.f;
    }
    __syncthreads();

    // ======== prefetch W tile 0 (hidden behind layer 1) ========
    const int sn = tid >> 1;        // W1 row 0..255
    const int kd = tid & 1;         // k16 half of the KC=32 tile
    float4 wv0, wv1, wv2, wv3;
    {
        const float4* wrow = reinterpret_cast<const float4*>(
            W1 + (size_t)sn * WIDTH + kd * 16);
        wv0 = wrow[0]; wv1 = wrow[1]; wv2 = wrow[2]; wv3 = wrow[3];
    }

    // ======== layer 1: thread c = tid&255 does 2 of 4 m-tiles ========
    {
        const int c    = tid & 255;
        const int half = tid >> 8;
        const int k8c = c >> 3, tgc = c & 3, khc = (c >> 2) & 1;
        float w0[DIN];
#pragma unroll
        for (int k = 0; k < DIN; k++) w0[k] = W0[c * DIN + k];
        const float bb = b0v[c];
#pragma unroll
        for (int mm = 0; mm < 2; mm++) {
            const int mi = half * 2 + mm;
#pragma unroll
            for (int g = 0; g < 8; g++) {
                const int r = mi * 16 + g;
                float sA = bb, sB = bb;
#pragma unroll
                for (int k = 0; k < DIN; k++) {
                    sA = fmaf(w0[k], sm[XS_OFF + r * DIN + k], sA);
                    sB = fmaf(w0[k], sm[XS_OFF + (r + 8) * DIN + k], sB);
                }
                float vA = tf32f(fmaxf(sA, 0.f));
                float vB = tf32f(fmaxf(sB, 0.f));
                *reinterpret_cast<ull*>(&sm[A1P(mi, k8c, g * 4 + tgc, 2 * khc)]) = pk(vA, vB);
            }
        }
    }
    __syncthreads();   // A1P complete; su fully dead -> WQ writable

    // store W tile 0 into buffer 0
    {
        float4 o;
        o = make_float4(tf32f(wv0.x), tf32f(wv1.x), tf32f(wv2.x), tf32f(wv3.x));
        *reinterpret_cast<float4*>(&sm[WQI(0, kd, 0, sn, 0)]) = o;
        o = make_float4(tf32f(wv0.y), tf32f(wv1.y), tf32f(wv2.y), tf32f(wv3.y));
        *reinterpret_cast<float4*>(&sm[WQI(0, kd, 1, sn, 0)]) = o;
        o = make_float4(tf32f(wv0.z), tf32f(wv1.z), tf32f(wv2.z), tf32f(wv3.z));
        *reinterpret_cast<float4*>(&sm[WQI(0, kd, 2, sn, 0)]) = o;
        o = make_float4(tf32f(wv0.w), tf32f(wv1.w), tf32f(wv2.w), tf32f(wv3.w));
        *reinterpret_cast<float4*>(&sm[WQI(0, kd, 3, sn, 0)]) = o;
    }
    __syncthreads();

    const int lane = tid & 31;
    const int wrp  = tid >> 5;
    const int wm   = wrp & 3;       // m16 group
    const int nq   = wrp >> 2;      // n64 quarter
    const int g    = lane >> 2;
    const int tg   = lane & 3;

    float acc[8][4];
#pragma unroll
    for (int t = 0; t < 8; t++)
#pragma unroll
        for (int e = 0; e < 4; e++) acc[t][e] = 0.f;

    // ======== mainloop: double-buffered W tiles, B-frag prefetch ========
    for (int kt = 0; kt < WIDTH / KC; kt++) {
        const int buf = kt & 1;
        // prefetch next tile's global data (overlaps with MMAs below)
        if (kt + 1 < WIDTH / KC) {
            const float4* wrow = reinterpret_cast<const float4*>(
                W1 + (size_t)sn * WIDTH + (kt + 1) * KC + kd * 16);
            wv0 = wrow[0]; wv1 = wrow[1]; wv2 = wrow[2]; wv3 = wrow[3];
        }

#pragma unroll
        for (int q = 0; q < 2; q++) {
            const int k8a = kt * 4 + 2 * q;
            float4 fa = *reinterpret_cast<const float4*>(&sm[A1P(wm, k8a, lane, 0)]);
            float4 fb = *reinterpret_cast<const float4*>(&sm[A1P(wm, k8a + 1, lane, 0)]);
            uint a00 = __float_as_uint(fa.x), a01 = __float_as_uint(fa.y);
            uint a02 = __float_as_uint(fa.z), a03 = __float_as_uint(fa.w);
            uint a10 = __float_as_uint(fb.x), a11 = __float_as_uint(fb.y);
            uint a12 = __float_as_uint(fb.z), a13 = __float_as_uint(fb.w);

            float4 bv = *reinterpret_cast<const float4*>(
                &sm[WQI(buf, q, tg, nq * 64 + g, 0)]);
#pragma unroll
            for (int t = 0; t < 8; t++) {
                float4 bvn;
                if (t < 7)
                    bvn = *reinterpret_cast<const float4*>(
                        &sm[WQI(buf, q, tg, nq * 64 + (t + 1) * 8 + g, 0)]);
                mma_tf32(acc[t][0], acc[t][1], acc[t][2], acc[t][3],
                         a00, a01, a02, a03,
                         __float_as_uint(bv.x), __float_as_uint(bv.y));
                mma_tf32(acc[t][0], acc[t][1], acc[t][2], acc[t][3],
                         a10, a11, a12, a13,
                         __float_as_uint(bv.z), __float_as_uint(bv.w));
                bv = bvn;
            }
        }

        if (kt + 1 < WIDTH / KC) {
            __syncthreads();   // everyone done reading buf (kt); safe to overwrite other buf
            const int nb = 1 - buf;
            float4 o;
            o = make_float4(tf32f(wv0.x), tf32f(wv1.x), tf32f(wv2.x), tf32f(wv3.x));
            *reinterpret_cast<float4*>(&sm[WQI(nb, kd, 0, sn, 0)]) = o;
            o = make_float4(tf32f(wv0.y), tf32f(wv1.y), tf32f(wv2.y), tf32f(wv3.y));
            *reinterpret_cast<float4*>(&sm[WQI(nb, kd, 1, sn, 0)]) = o;
            o = make_float4(tf32f(wv0.z), tf32f(wv1.z), tf32f(wv2.z), tf32f(wv3.z));
            *reinterpret_cast<float4*>(&sm[WQI(nb, kd, 2, sn, 0)]) = o;
            o = make_float4(tf32f(wv0.w), tf32f(wv1.w), tf32f(wv2.w), tf32f(wv3.w));
            *reinterpret_cast<float4*>(&sm[WQI(nb, kd, 3, sn, 0)]) = o;
            __syncthreads();
        }
    }

    // ======== epilogue: bias + relu + dot W2, reduce tg, shared atomics =====
    float qa = 0.f, qb = 0.f;
#pragma unroll
    for (int t = 0; t < 8; t++) {
        const int c0 = nq * 64 + t * 8 + 2 * tg;
        float2 bb = *reinterpret_cast<const float2*>(b1 + c0);
        float2 ww = *reinterpret_cast<const float2*>(W2 + c0);
        qa = fmaf(ww.x, fmaxf(acc[t][0] + bb.x, 0.f), qa);
        qa = fmaf(ww.y, fmaxf(acc[t][1] + bb.y, 0.f), qa);
        qb = fmaf(ww.x, fmaxf(acc[t][2] + bb.x, 0.f), qb);
        qb = fmaf(ww.y, fmaxf(acc[t][3] + bb.y, 0.f), qb);
    }
    qa += __shfl_xor_sync(0xffffffffu, qa, 1);
    qa += __shfl_xor_sync(0xffffffffu, qa, 2);
    qb += __shfl_xor_sync(0xffffffffu, qb, 1);
    qb += __shfl_xor_sync(0xffffffffu, qb, 2);
    if (tg == 0) {
        atomicAdd(&sm[QS_OFF + wm * 16 + g], qa);
        atomicAdd(&sm[QS_OFF + wm * 16 + g + 8], qb);
    }
    __syncthreads();
    if (tid < RPB)
        out[row0 + tid] = sm[QS_OFF + tid] + b2[0];
}

// ---------------------------------------------------------------------------
extern "C" void kernel_launch(void* const* d_in, const int* in_sizes, int n_in,
                              void* d_out, int out_size)
{
    const float* state   = (const float*)d_in[0];
    const float* ctrlseq = (const float*)d_in[1];
    const float* control = (const float*)d_in[2];
    const float* WA      = (const float*)d_in[3];
    const float* WB      = (const float*)d_in[4];
    const float* W0      = (const float*)d_in[5];
    const float* b0      = (const float*)d_in[6];
    const float* W1      = (const float*)d_in[7];
    const float* b1      = (const float*)d_in[8];
    const float* W2      = (const float*)d_in[9];
    const float* b2      = (const float*)d_in[10];
    float* out           = (float*)d_out;

    const int smem_bytes = SMEMF * (int)sizeof(float);   // 136576 B
    cudaFuncSetAttribute(fused_kernel,
                         cudaFuncAttributeMaxDynamicSharedMemorySize, smem_bytes);

    fused_kernel<<<BSZ / RPB, DEC_T, smem_bytes>>>(
        state, ctrlseq, control, WA, WB, W0, b0, W1, b1, W2, b2, out);
    (void)in_sizes; (void)n_in; (void)out_size;
}